// round 1
// baseline (speedup 1.0000x reference)
#include <cuda_runtime.h>
#include <cuda_bf16.h>
#include <math.h>
#include <stdint.h>

// Problem constants
#define BB   2
#define SS   2048
#define EE   1024
#define HH   16
#define DD   64
#define HALF 32
#define MROWS 4096            // B*S
#define NQKV  1152            // H*D + D + D
#define EPSF  1.1920929e-07f  // finfo(float32).eps

// ---------------- device scratch (static, allocation-free) ----------------
__device__ float g_Wqkv[1024 * NQKV];   // packed [Wq | Wk | Wv], k-major rows
__device__ float g_qkv[MROWS * NQKV];   // projections, later rope/normed in place
__device__ float g_attn[MROWS * EE];    // attention output (B,S,H*D)

// ---------------- pack Wq|Wk|Wv ----------------
__global__ void pack_kernel(const float* __restrict__ Wq,
                            const float* __restrict__ Wk,
                            const float* __restrict__ Wv,
                            float* __restrict__ Wqkv)
{
    int idx = blockIdx.x * blockDim.x + threadIdx.x;
    if (idx >= 1024 * NQKV) return;
    int k = idx / NQKV;
    int n = idx - k * NQKV;
    float v;
    if (n < 1024)       v = Wq[k * 1024 + n];
    else if (n < 1088)  v = Wk[k * 64 + (n - 1024)];
    else                v = Wv[k * 64 + (n - 1088)];
    Wqkv[idx] = v;
}

// ---------------- generic 128x128x8 SGEMM, 8x8 micro-tiles ----------------
// C[M,N] = A[M,K] @ B[K,N]; M%128==0, N%128==0, K%8==0 (true for all our uses)
__global__ __launch_bounds__(256, 2)
void sgemm128(const float* __restrict__ A, const float* __restrict__ B,
              float* __restrict__ C, int K, int lda, int ldb, int ldc)
{
    __shared__ float As[8][132];   // transposed A tile, padded
    __shared__ float Bs[8][132];

    int tid = threadIdx.x;
    int ty = tid >> 4;          // 0..15
    int tx = tid & 15;          // 0..15
    size_t m0 = (size_t)blockIdx.y * 128;
    size_t n0 = (size_t)blockIdx.x * 128;

    int arow = tid >> 1;              // 0..127
    int ak   = (tid & 1) * 4;         // 0 or 4
    int brow = tid >> 5;              // 0..7
    int bcol = (tid & 31) * 4;        // 0..124

    const float* Ap = A + (m0 + arow) * (size_t)lda + ak;
    const float* Bp = B + (size_t)brow * ldb + n0 + bcol;

    float4 a_n = *(const float4*)Ap;
    float4 b_n = *(const float4*)Bp;

    float acc[8][8];
    #pragma unroll
    for (int i = 0; i < 8; i++)
        #pragma unroll
        for (int j = 0; j < 8; j++) acc[i][j] = 0.f;

    for (int k0 = 0; k0 < K; k0 += 8) {
        As[ak + 0][arow] = a_n.x;
        As[ak + 1][arow] = a_n.y;
        As[ak + 2][arow] = a_n.z;
        As[ak + 3][arow] = a_n.w;
        *(float4*)&Bs[brow][bcol] = b_n;
        __syncthreads();

        if (k0 + 8 < K) {
            a_n = *(const float4*)(Ap + k0 + 8);
            b_n = *(const float4*)(Bp + (size_t)(k0 + 8) * ldb);
        }

        #pragma unroll
        for (int kk = 0; kk < 8; kk++) {
            float4 a0 = *(const float4*)&As[kk][ty * 4];
            float4 a1 = *(const float4*)&As[kk][64 + ty * 4];
            float4 b0 = *(const float4*)&Bs[kk][tx * 4];
            float4 b1 = *(const float4*)&Bs[kk][64 + tx * 4];
            float ar[8] = {a0.x, a0.y, a0.z, a0.w, a1.x, a1.y, a1.z, a1.w};
            float br[8] = {b0.x, b0.y, b0.z, b0.w, b1.x, b1.y, b1.z, b1.w};
            #pragma unroll
            for (int i = 0; i < 8; i++)
                #pragma unroll
                for (int j = 0; j < 8; j++)
                    acc[i][j] = fmaf(ar[i], br[j], acc[i][j]);
        }
        __syncthreads();
    }

    #pragma unroll
    for (int i = 0; i < 8; i++) {
        size_t row = m0 + (i < 4 ? (ty * 4 + i) : (64 + ty * 4 + (i - 4)));
        float4 c0 = make_float4(acc[i][0], acc[i][1], acc[i][2], acc[i][3]);
        float4 c1 = make_float4(acc[i][4], acc[i][5], acc[i][6], acc[i][7]);
        *(float4*)&C[row * (size_t)ldc + n0 + tx * 4]      = c0;
        *(float4*)&C[row * (size_t)ldc + n0 + 64 + tx * 4] = c1;
    }
}

// ---------------- RoPE + RMSNorm (q,k) and gated ve add (v), in place -----
// one warp per 64-dim vector; 18 vectors per (b,s): 16 q heads, 1 k, 1 v
__global__ __launch_bounds__(256)
void post_kernel(const float* __restrict__ x, const float* __restrict__ ve,
                 const float* __restrict__ cosb, const float* __restrict__ sinb,
                 const float* __restrict__ Wg, float* __restrict__ qkv)
{
    int wid  = (blockIdx.x * blockDim.x + threadIdx.x) >> 5;
    int lane = threadIdx.x & 31;
    int row = wid / 18;
    int t   = wid - row * 18;
    if (row >= MROWS) return;
    int s = row & (SS - 1);

    if (t < 17) {
        // rope + rmsnorm: q head t (t<16) or k (t==16)
        float* vec = qkv + (size_t)row * NQKV + (t < 16 ? t * 64 : 1024);
        float c  = cosb[s * HALF + lane];
        float sn = sinb[s * HALF + lane];
        float x1 = vec[lane];
        float x2 = vec[lane + 32];
        float y1 = x1 * c + x2 * sn;
        float y2 = x2 * c - x1 * sn;
        float ssum = y1 * y1 + y2 * y2;
        #pragma unroll
        for (int off = 16; off; off >>= 1)
            ssum += __shfl_xor_sync(0xffffffffu, ssum, off);
        float sc = rsqrtf(ssum * (1.0f / 64.0f) + EPSF);
        vec[lane]      = y1 * sc;
        vec[lane + 32] = y2 * sc;
    } else {
        // v += 2*sigmoid(x[:32]@Wg) * ve
        float g = x[(size_t)row * EE + lane] * Wg[lane];
        #pragma unroll
        for (int off = 16; off; off >>= 1)
            g += __shfl_xor_sync(0xffffffffu, g, off);
        float gate = 2.0f / (1.0f + __expf(-g));
        float* vvec = qkv + (size_t)row * NQKV + 1088;
        const float* veb = ve + (size_t)row * DD;
        vvec[lane]      += gate * veb[lane];
        vvec[lane + 32] += gate * veb[lane + 32];
    }
}

// ---------------- windowed-causal flash attention ----------------
// grid (32 q-tiles, 16 heads, 2 batch), 256 threads; 64-query x 64-key tiles
#define ATP 68   // padded row stride (floats), float4-aligned
__global__ __launch_bounds__(256)
void attn_kernel(const float* __restrict__ qkv, float* __restrict__ out,
                 const int* __restrict__ wptr)
{
    extern __shared__ float sm[];
    float* Qt = sm;               // [64 d][68] : Qt[d*ATP + q]
    float* Kt = sm + 64 * ATP;    // [64 d][68] : Kt[d*ATP + k]
    float* Vs = sm + 2 * 64 * ATP;// [64 k][68] : Vs[k*ATP + d]
    float* Ps = sm + 3 * 64 * ATP;// [64 q][68] : Ps[q*ATP + k]

    const int window = *wptr;
    int tid = threadIdx.x;
    int ty = tid >> 4;            // 0..15
    int tx = tid & 15;            // 0..15
    int qt = blockIdx.x;
    int h  = blockIdx.y;
    int b  = blockIdx.z;
    int q0 = qt * 64;
    const float* base = qkv + (size_t)b * SS * NQKV;

    // load Q tile (scaled by D^-1/2), transposed to d-major
    for (int idx = tid; idx < 4096; idx += 256) {
        int qq = idx >> 6, d = idx & 63;
        Qt[d * ATP + qq] = base[(size_t)(q0 + qq) * NQKV + h * 64 + d] * 0.125f;
    }

    float o[4][4];
    #pragma unroll
    for (int i = 0; i < 4; i++)
        #pragma unroll
        for (int j = 0; j < 4; j++) o[i][j] = 0.f;
    float mrow[4], lrow[4];
    #pragma unroll
    for (int i = 0; i < 4; i++) { mrow[i] = -INFINITY; lrow[i] = 0.f; }

    int lo = q0 - window + 1; if (lo < 0) lo = 0;
    int t_lo = lo >> 6;

    for (int t = t_lo; t <= qt; t++) {
        int k0 = t * 64;
        __syncthreads();   // protect Kt/Vs/Ps from previous iteration (and Qt first time)
        for (int idx = tid; idx < 4096; idx += 256) {
            int kk = idx >> 6, d = idx & 63;
            Kt[d * ATP + kk] = base[(size_t)(k0 + kk) * NQKV + 1024 + d];
            Vs[kk * ATP + d] = base[(size_t)(k0 + kk) * NQKV + 1088 + d];
        }
        __syncthreads();

        // S = Q K^T  (rows q = ty*4+i, cols k = tx*4+j)
        float sreg[4][4];
        #pragma unroll
        for (int i = 0; i < 4; i++)
            #pragma unroll
            for (int j = 0; j < 4; j++) sreg[i][j] = 0.f;
        #pragma unroll 16
        for (int d = 0; d < 64; d++) {
            float4 a = *(const float4*)&Qt[d * ATP + ty * 4];
            float4 kb = *(const float4*)&Kt[d * ATP + tx * 4];
            float av[4] = {a.x, a.y, a.z, a.w};
            float kv[4] = {kb.x, kb.y, kb.z, kb.w};
            #pragma unroll
            for (int i = 0; i < 4; i++)
                #pragma unroll
                for (int j = 0; j < 4; j++)
                    sreg[i][j] = fmaf(av[i], kv[j], sreg[i][j]);
        }

        // mask
        #pragma unroll
        for (int i = 0; i < 4; i++) {
            int q = q0 + ty * 4 + i;
            #pragma unroll
            for (int j = 0; j < 4; j++) {
                int k = k0 + tx * 4 + j;
                int dist = q - k;
                if (dist < 0 || dist >= window) sreg[i][j] = -INFINITY;
            }
        }

        // online softmax update (per-row reduce across 16 tx lanes)
        #pragma unroll
        for (int i = 0; i < 4; i++) {
            float pm = fmaxf(fmaxf(sreg[i][0], sreg[i][1]),
                             fmaxf(sreg[i][2], sreg[i][3]));
            #pragma unroll
            for (int off = 8; off; off >>= 1)
                pm = fmaxf(pm, __shfl_xor_sync(0xffffffffu, pm, off));
            float mnew = fmaxf(mrow[i], pm);
            float p0 = (sreg[i][0] == -INFINITY) ? 0.f : __expf(sreg[i][0] - mnew);
            float p1 = (sreg[i][1] == -INFINITY) ? 0.f : __expf(sreg[i][1] - mnew);
            float p2 = (sreg[i][2] == -INFINITY) ? 0.f : __expf(sreg[i][2] - mnew);
            float p3 = (sreg[i][3] == -INFINITY) ? 0.f : __expf(sreg[i][3] - mnew);
            sreg[i][0] = p0; sreg[i][1] = p1; sreg[i][2] = p2; sreg[i][3] = p3;
            float rs = p0 + p1 + p2 + p3;
            #pragma unroll
            for (int off = 8; off; off >>= 1)
                rs += __shfl_xor_sync(0xffffffffu, rs, off);
            float corr = (mrow[i] == -INFINITY) ? 0.f : __expf(mrow[i] - mnew);
            lrow[i] = lrow[i] * corr + rs;
            mrow[i] = mnew;
            #pragma unroll
            for (int j = 0; j < 4; j++) o[i][j] *= corr;
            *(float4*)&Ps[(ty * 4 + i) * ATP + tx * 4] =
                make_float4(p0, p1, p2, p3);
        }
        __syncthreads();

        // O += P @ V   (rows q = ty*4+i, cols d = tx*4+j)
        #pragma unroll 8
        for (int kk = 0; kk < 64; kk++) {
            float4 v = *(const float4*)&Vs[kk * ATP + tx * 4];
            float vv[4] = {v.x, v.y, v.z, v.w};
            float pr0 = Ps[(ty * 4 + 0) * ATP + kk];
            float pr1 = Ps[(ty * 4 + 1) * ATP + kk];
            float pr2 = Ps[(ty * 4 + 2) * ATP + kk];
            float pr3 = Ps[(ty * 4 + 3) * ATP + kk];
            #pragma unroll
            for (int j = 0; j < 4; j++) {
                o[0][j] = fmaf(pr0, vv[j], o[0][j]);
                o[1][j] = fmaf(pr1, vv[j], o[1][j]);
                o[2][j] = fmaf(pr2, vv[j], o[2][j]);
                o[3][j] = fmaf(pr3, vv[j], o[3][j]);
            }
        }
    }

    // finalize + write (B,S,H*D)
    #pragma unroll
    for (int i = 0; i < 4; i++) {
        float inv = 1.0f / lrow[i];
        float4 r = make_float4(o[i][0] * inv, o[i][1] * inv,
                               o[i][2] * inv, o[i][3] * inv);
        size_t row = (size_t)b * SS + q0 + ty * 4 + i;
        *(float4*)&out[row * EE + h * 64 + tx * 4] = r;
    }
}

#define ATT_SMEM (4 * 64 * ATP * sizeof(float))   // 69,632 B

// ---------------- launch ----------------
extern "C" void kernel_launch(void* const* d_in, const int* in_sizes, int n_in,
                              void* d_out, int out_size)
{
    const float* x    = (const float*)d_in[0];
    const float* ve   = (const float*)d_in[1];
    const float* cosb = (const float*)d_in[2];
    const float* sinb = (const float*)d_in[3];
    const float* Wq   = (const float*)d_in[4];
    const float* Wk   = (const float*)d_in[5];
    const float* Wv   = (const float*)d_in[6];
    const float* Wo   = (const float*)d_in[7];
    const float* Wg   = (const float*)d_in[8];
    const int*   win  = (const int*)d_in[9];
    float* out = (float*)d_out;

    float *wqkv, *qkv, *attn;
    cudaGetSymbolAddress((void**)&wqkv, g_Wqkv);
    cudaGetSymbolAddress((void**)&qkv,  g_qkv);
    cudaGetSymbolAddress((void**)&attn, g_attn);

    cudaFuncSetAttribute(attn_kernel,
                         cudaFuncAttributeMaxDynamicSharedMemorySize,
                         (int)ATT_SMEM);

    // 1. pack weights
    pack_kernel<<<(1024 * NQKV + 255) / 256, 256>>>(Wq, Wk, Wv, wqkv);

    // 2. fused QKV projection: [4096,1024] @ [1024,1152]
    sgemm128<<<dim3(NQKV / 128, MROWS / 128), 256>>>(x, wqkv, qkv,
                                                     1024, 1024, NQKV, NQKV);

    // 3. rope + rmsnorm (q,k), gated ve add (v)
    post_kernel<<<(MROWS * 18) / 8, 256>>>(x, ve, cosb, sinb, Wg, qkv);

    // 4. attention
    attn_kernel<<<dim3(SS / 64, HH, BB), 256, ATT_SMEM>>>(qkv, attn, win);

    // 5. output projection: [4096,1024] @ [1024,1024]
    sgemm128<<<dim3(EE / 128, MROWS / 128), 256>>>(attn, Wo, out,
                                                   1024, 1024, EE, EE);
}